// round 2
// baseline (speedup 1.0000x reference)
#include <cuda_runtime.h>
#include <cstdint>

#define NU_MAX 50000
#define NI_MAX 50000
#define E_MAX  100000

// ---------------- device scratch (static; no allocations allowed) ----------
__device__ float g_v_u[NU_MAX * 512];     // V projection, user
__device__ float g_v_i[NI_MAX * 512];     // V projection, item
__device__ float g_aqk_u[NU_MAX * 16];    // per node: [0..7]=aq, [8..15]=ak
__device__ float g_aqk_i[NI_MAX * 16];
__device__ float g_A_u[16 * 256];         // effective attn proj: rows 0..7 q, 8..15 k
__device__ float g_A_i[16 * 256];
__device__ float g_beff_u[16];
__device__ float g_beff_i[16];
__device__ unsigned g_mkey[NU_MAX * 8];   // ordered-uint encoded segment max
__device__ float g_den[NU_MAX * 8];
__device__ float g_deg[NU_MAX];
__device__ float g_edge[E_MAX * 8];       // score -> exp -> attn (in place)

// ---------------- helpers ----------------
__device__ __forceinline__ unsigned fkey(float f) {
    unsigned u = __float_as_uint(f);
    return (u & 0x80000000u) ? ~u : (u | 0x80000000u);
}
__device__ __forceinline__ float keyf(unsigned k) {
    unsigned u = (k & 0x80000000u) ? (k & 0x7fffffffu) : ~k;
    return __uint_as_float(u);
}

__device__ __forceinline__ void fma2(unsigned long long& c, unsigned long long a,
                                     unsigned long long b) {
    asm("fma.rn.f32x2 %0, %1, %2, %0;" : "+l"(c) : "l"(a), "l"(b));
}
__device__ __forceinline__ unsigned long long dup2(float v) {
    unsigned long long r;
    asm("mov.b64 %0, {%1, %1};" : "=l"(r) : "f"(v));
    return r;
}
__device__ __forceinline__ float2 unpk(unsigned long long v) {
    float lo, hi;
    asm("mov.b64 {%0, %1}, %2;" : "=f"(lo), "=f"(hi) : "l"(v));
    return make_float2(lo, hi);
}

union F4U { float4 f; unsigned long long u[2]; };

// ---------------- prep: fold wa into Wq/Wk -> effective [16,256] matrices ---
__global__ void prep_kernel(const float* __restrict__ Wq_u, const float* __restrict__ bq_u,
                            const float* __restrict__ Wk_u, const float* __restrict__ bk_u,
                            const float* __restrict__ Wq_i, const float* __restrict__ bq_i,
                            const float* __restrict__ Wk_i, const float* __restrict__ bk_i,
                            const float* __restrict__ wa_u, const float* __restrict__ wa_i) {
    int b = blockIdx.x;  // 0:Wq_u 1:Wk_u 2:Wq_i 3:Wk_i
    const float* W    = (b == 0) ? Wq_u : (b == 1) ? Wk_u : (b == 2) ? Wq_i : Wk_i;
    const float* bias = (b == 0) ? bq_u : (b == 1) ? bk_u : (b == 2) ? bq_i : bk_i;
    const float* wa   = (b < 2) ? wa_u : wa_i;
    float* A  = (b < 2) ? g_A_u : g_A_i;
    float* be = (b < 2) ? g_beff_u : g_beff_i;
    int rowoff = (b & 1) * 8;
    int k = threadIdx.x;
    __shared__ float was[64];
    if (k < 64) was[k] = wa[k];
    __syncthreads();
#pragma unroll
    for (int h = 0; h < 8; h++) {
        float s = 0.f;
        for (int d = 0; d < 64; d++) s += W[(h * 64 + d) * 256 + k] * was[d];
        A[(rowoff + h) * 256 + k] = s;
    }
    if (k < 8) {
        float s = 0.f;
        for (int d = 0; d < 64; d++) s += bias[k * 64 + d] * was[d];
        be[rowoff + k] = s;
    }
}

// ---------------- attn projections: aq/ak = x @ A^T + beff  (16 outs/node) --
__global__ void attnproj_kernel(const float* __restrict__ X, int isUser) {
    const float* A  = isUser ? g_A_u : g_A_i;
    const float* be = isUser ? g_beff_u : g_beff_i;
    float* outp     = isUser ? g_aqk_u : g_aqk_i;
    __shared__ float xs[256];
    int n = blockIdx.x;
    xs[threadIdx.x] = X[(size_t)n * 256 + threadIdx.x];
    __syncthreads();
    int w = threadIdx.x >> 5, l = threadIdx.x & 31;
#pragma unroll
    for (int r = 0; r < 2; r++) {
        int j = w + r * 8;
        float s = 0.f;
#pragma unroll
        for (int c = 0; c < 8; c++) {
            int k = l + 32 * c;
            s += xs[k] * A[j * 256 + k];
        }
#pragma unroll
        for (int off = 16; off; off >>= 1) s += __shfl_down_sync(0xffffffffu, s, off);
        if (l == 0) outp[n * 16 + j] = s + be[j];
    }
}

// ---------------- V GEMM: C[M,512] = X[M,256] @ W[512,256]^T + b  (f32x2) ---
__global__ void __launch_bounds__(256) gemm_kernel(const float* __restrict__ X,
                                                   const float* __restrict__ W,
                                                   const float* __restrict__ bias,
                                                   int isUser, int M) {
    float* C = isUser ? g_v_u : g_v_i;
    __shared__ float Xs[16][132];                // k-major X tile (padded)
    __shared__ unsigned long long Wsd[16][64];   // W values pre-duplicated into both halves
    int tid = threadIdx.x;
    int tx = tid & 15, ty = tid >> 4;
    int m0 = blockIdx.x * 128;
    int n0 = blockIdx.y * 64;

    unsigned long long acc[4][4];
#pragma unroll
    for (int p = 0; p < 4; p++)
#pragma unroll
        for (int j = 0; j < 4; j++) acc[p][j] = 0ULL;

    for (int k0 = 0; k0 < 256; k0 += 16) {
#pragma unroll
        for (int it = 0; it < 2; it++) {
            int jj = it * 256 + tid;
            int row = jj >> 2, kq = jj & 3;
            int gr = m0 + row;
            if (gr > M - 1) gr = M - 1;
            float4 v = *(const float4*)(X + (size_t)gr * 256 + k0 + kq * 4);
            Xs[kq * 4 + 0][row] = v.x;
            Xs[kq * 4 + 1][row] = v.y;
            Xs[kq * 4 + 2][row] = v.z;
            Xs[kq * 4 + 3][row] = v.w;
        }
        {
            int row = tid >> 2, kq = tid & 3;  // row = n index 0..63
            float4 v = *(const float4*)(W + (size_t)(n0 + row) * 256 + k0 + kq * 4);
            Wsd[kq * 4 + 0][row] = dup2(v.x);
            Wsd[kq * 4 + 1][row] = dup2(v.y);
            Wsd[kq * 4 + 2][row] = dup2(v.z);
            Wsd[kq * 4 + 3][row] = dup2(v.w);
        }
        __syncthreads();
#pragma unroll
        for (int kk = 0; kk < 16; kk++) {
            F4U a0, a1;
            a0.f = *(const float4*)&Xs[kk][ty * 8];
            a1.f = *(const float4*)&Xs[kk][ty * 8 + 4];
            ulonglong2 b01 = *(const ulonglong2*)&Wsd[kk][tx * 4];
            ulonglong2 b23 = *(const ulonglong2*)&Wsd[kk][tx * 4 + 2];
            unsigned long long ap[4] = {a0.u[0], a0.u[1], a1.u[0], a1.u[1]};
            unsigned long long bb[4] = {b01.x, b01.y, b23.x, b23.y};
#pragma unroll
            for (int p = 0; p < 4; p++)
#pragma unroll
                for (int j = 0; j < 4; j++) fma2(acc[p][j], ap[p], bb[j]);
        }
        __syncthreads();
    }
    float4 bv = *(const float4*)(bias + n0 + tx * 4);
#pragma unroll
    for (int p = 0; p < 4; p++) {
        float2 c0 = unpk(acc[p][0]), c1 = unpk(acc[p][1]);
        float2 c2 = unpk(acc[p][2]), c3 = unpk(acc[p][3]);
        int r0 = m0 + ty * 8 + 2 * p;
        if (r0 < M) {
            float4 o = make_float4(c0.x + bv.x, c1.x + bv.y, c2.x + bv.z, c3.x + bv.w);
            *(float4*)(C + (size_t)r0 * 512 + n0 + tx * 4) = o;
        }
        if (r0 + 1 < M) {
            float4 o = make_float4(c0.y + bv.x, c1.y + bv.y, c2.y + bv.z, c3.y + bv.w);
            *(float4*)(C + (size_t)(r0 + 1) * 512 + n0 + tx * 4) = o;
        }
    }
}

// ---------------- edge phase ----------------
__global__ void score_kernel(const int* __restrict__ src, const int* __restrict__ dst,
                             int srcUser, int dstUser, int E) {
    int e = blockIdx.x * blockDim.x + threadIdx.x;
    if (e >= E) return;
    const float* aqk_s = srcUser ? g_aqk_u : g_aqk_i;
    const float* aqk_d = dstUser ? g_aqk_u : g_aqk_i;
    int s = src[e], d = dst[e];
    float4 ak0 = *(const float4*)(aqk_s + s * 16 + 8);
    float4 ak1 = *(const float4*)(aqk_s + s * 16 + 12);
    float4 aq0 = *(const float4*)(aqk_d + d * 16);
    float4 aq1 = *(const float4*)(aqk_d + d * 16 + 4);
    float sc[8];
    sc[0] = (ak0.x + aq0.x) * 0.125f; sc[1] = (ak0.y + aq0.y) * 0.125f;
    sc[2] = (ak0.z + aq0.z) * 0.125f; sc[3] = (ak0.w + aq0.w) * 0.125f;
    sc[4] = (ak1.x + aq1.x) * 0.125f; sc[5] = (ak1.y + aq1.y) * 0.125f;
    sc[6] = (ak1.z + aq1.z) * 0.125f; sc[7] = (ak1.w + aq1.w) * 0.125f;
    *(float4*)(g_edge + e * 8)     = make_float4(sc[0], sc[1], sc[2], sc[3]);
    *(float4*)(g_edge + e * 8 + 4) = make_float4(sc[4], sc[5], sc[6], sc[7]);
#pragma unroll
    for (int h = 0; h < 8; h++) atomicMax(&g_mkey[d * 8 + h], fkey(sc[h]));
    atomicAdd(&g_deg[d], 1.0f);
}

__global__ void exp_kernel(const int* __restrict__ dst, int E) {
    int e = blockIdx.x * blockDim.x + threadIdx.x;
    if (e >= E) return;
    int d = dst[e];
    float4 s0 = *(const float4*)(g_edge + e * 8);
    float4 s1 = *(const float4*)(g_edge + e * 8 + 4);
    float sc[8] = {s0.x, s0.y, s0.z, s0.w, s1.x, s1.y, s1.z, s1.w};
    float ex[8];
#pragma unroll
    for (int h = 0; h < 8; h++) {
        float m = keyf(g_mkey[d * 8 + h]);
        ex[h] = __expf(sc[h] - m);
        atomicAdd(&g_den[d * 8 + h], ex[h]);
    }
    *(float4*)(g_edge + e * 8)     = make_float4(ex[0], ex[1], ex[2], ex[3]);
    *(float4*)(g_edge + e * 8 + 4) = make_float4(ex[4], ex[5], ex[6], ex[7]);
}

__global__ void attn_kernel(const int* __restrict__ dst, int E) {
    int e = blockIdx.x * blockDim.x + threadIdx.x;
    if (e >= E) return;
    int d = dst[e];
    float id = 1.0f / fmaxf(g_deg[d], 1.0f);
    float4 e0 = *(const float4*)(g_edge + e * 8);
    float4 e1 = *(const float4*)(g_edge + e * 8 + 4);
    float ex[8] = {e0.x, e0.y, e0.z, e0.w, e1.x, e1.y, e1.z, e1.w};
    float a[8];
#pragma unroll
    for (int h = 0; h < 8; h++) a[h] = ex[h] / g_den[d * 8 + h] * id;
    *(float4*)(g_edge + e * 8)     = make_float4(a[0], a[1], a[2], a[3]);
    *(float4*)(g_edge + e * 8 + 4) = make_float4(a[4], a[5], a[6], a[7]);
}

// message scatter: one thread per (edge, float4-quad); contiguous 2KB per edge
__global__ void msg_kernel(const int* __restrict__ src, const int* __restrict__ dst,
                           int srcUser, float* __restrict__ outp, int E) {
    int idx = blockIdx.x * blockDim.x + threadIdx.x;
    if (idx >= E * 128) return;
    int e = idx >> 7, q = idx & 127;
    int h = q >> 4;
    const float* v = srcUser ? g_v_u : g_v_i;
    int s = src[e], d = dst[e];
    float a = g_edge[e * 8 + h];
    float4 vv = *(const float4*)(v + (size_t)s * 512 + q * 4);
    float x = vv.x * a, y = vv.y * a, z = vv.z * a, w = vv.w * a;
    float* p = outp + (size_t)d * 512 + q * 4;
    asm volatile("red.global.add.v4.f32 [%0], {%1,%2,%3,%4};"
                 :: "l"(p), "f"(x), "f"(y), "f"(z), "f"(w)
                 : "memory");
}

// ---------------- host ----------------
static void run_etype(const int* src, const int* dst, int srcUser, int dstUser,
                      float* outp, int Nd, int E,
                      void* p_mkey, void* p_den, void* p_deg) {
    cudaMemsetAsync(p_mkey, 0, (size_t)Nd * 8 * sizeof(unsigned));
    cudaMemsetAsync(p_den, 0, (size_t)Nd * 8 * sizeof(float));
    cudaMemsetAsync(p_deg, 0, (size_t)Nd * sizeof(float));
    int gb = (E + 255) / 256;
    score_kernel<<<gb, 256>>>(src, dst, srcUser, dstUser, E);
    exp_kernel<<<gb, 256>>>(dst, E);
    attn_kernel<<<gb, 256>>>(dst, E);
    msg_kernel<<<(E * 128 + 255) / 256, 256>>>(src, dst, srcUser, outp, E);
}

extern "C" void kernel_launch(void* const* d_in, const int* in_sizes, int n_in,
                              void* d_out, int out_size) {
    const float* x_u  = (const float*)d_in[0];
    const float* x_i  = (const float*)d_in[1];
    const float* Wq_u = (const float*)d_in[2];  const float* bq_u = (const float*)d_in[3];
    const float* Wk_u = (const float*)d_in[4];  const float* bk_u = (const float*)d_in[5];
    const float* Wv_u = (const float*)d_in[6];  const float* bv_u = (const float*)d_in[7];
    const float* Wq_i = (const float*)d_in[8];  const float* bq_i = (const float*)d_in[9];
    const float* Wk_i = (const float*)d_in[10]; const float* bk_i = (const float*)d_in[11];
    const float* Wv_i = (const float*)d_in[12]; const float* bv_i = (const float*)d_in[13];
    const float* wa_u = (const float*)d_in[14]; const float* wa_i = (const float*)d_in[15];
    const int* src_c  = (const int*)d_in[16];   const int* dst_c  = (const int*)d_in[17];
    const int* src_cb = (const int*)d_in[18];   const int* dst_cb = (const int*)d_in[19];
    const int* src_f  = (const int*)d_in[20];   const int* dst_f  = (const int*)d_in[21];

    int NU = in_sizes[0] / 256;
    int NI = in_sizes[1] / 256;
    int E  = in_sizes[16];

    float* out_user = (float*)d_out;
    float* out_item = out_user + (size_t)NU * 512;

    void *p_mkey, *p_den, *p_deg;
    cudaGetSymbolAddress(&p_mkey, g_mkey);
    cudaGetSymbolAddress(&p_den, g_den);
    cudaGetSymbolAddress(&p_deg, g_deg);

    cudaMemsetAsync(d_out, 0, (size_t)(NU + NI) * 512 * sizeof(float));

    prep_kernel<<<4, 256>>>(Wq_u, bq_u, Wk_u, bk_u, Wq_i, bq_i, Wk_i, bk_i, wa_u, wa_i);
    attnproj_kernel<<<NU, 256>>>(x_u, 1);
    attnproj_kernel<<<NI, 256>>>(x_i, 0);
    gemm_kernel<<<dim3((NU + 127) / 128, 8), 256>>>(x_u, Wv_u, bv_u, 1, NU);
    gemm_kernel<<<dim3((NI + 127) / 128, 8), 256>>>(x_i, Wv_i, bv_i, 0, NI);

    // ('user','clicks','item'): src=user, dst=item -> h_item
    run_etype(src_c, dst_c, 1, 0, out_item, NI, E, p_mkey, p_den, p_deg);
    // ('item','clicked_by','user'): src=item, dst=user -> h_user
    run_etype(src_cb, dst_cb, 0, 1, out_user, NU, E, p_mkey, p_den, p_deg);
    // ('user','follows','user') -> h_user (accumulates)
    run_etype(src_f, dst_f, 1, 1, out_user, NU, E, p_mkey, p_den, p_deg);
}

// round 4
// speedup vs baseline: 1.9389x; 1.9389x over previous
#include <cuda_runtime.h>
#include <cstdint>

#define NU_MAX 50000
#define NI_MAX 50000
#define E_MAX  100000

// ---------------- device scratch (static; no allocations allowed) ----------
__device__ float g_v_u[NU_MAX * 512];     // V projection, user
__device__ float g_v_i[NI_MAX * 512];     // V projection, item
__device__ float g_aqk_u[NU_MAX * 16];    // per node: [0..7]=aq, [8..15]=ak
__device__ float g_aqk_i[NI_MAX * 16];
__device__ float g_A_u[16 * 256];         // effective attn proj: rows 0..7 q, 8..15 k
__device__ float g_A_i[16 * 256];
__device__ float g_beff_u[16];
__device__ float g_beff_i[16];
__device__ unsigned g_mkey[NU_MAX * 8];   // ordered-uint encoded segment max
__device__ float g_den[NU_MAX * 8];
__device__ float g_deg[NU_MAX];
__device__ float g_edge[E_MAX * 8];       // score -> exp -> attn (in place)

// ---------------- helpers ----------------
__device__ __forceinline__ unsigned fkey(float f) {
    unsigned u = __float_as_uint(f);
    return (u & 0x80000000u) ? ~u : (u | 0x80000000u);
}
__device__ __forceinline__ float keyf(unsigned k) {
    unsigned u = (k & 0x80000000u) ? (k & 0x7fffffffu) : ~k;
    return __uint_as_float(u);
}
__device__ __forceinline__ uint32_t to_tf32(float f) {
    uint32_t r;
    asm("cvt.rna.tf32.f32 %0, %1;" : "=r"(r) : "f"(f));
    return r;
}
__device__ __forceinline__ void mma_tf32(float* c, uint32_t a0, uint32_t a1,
                                         uint32_t a2, uint32_t a3,
                                         uint32_t b0, uint32_t b1) {
    asm("mma.sync.aligned.m16n8k8.row.col.f32.tf32.tf32.f32 "
        "{%0,%1,%2,%3}, {%4,%5,%6,%7}, {%8,%9}, {%0,%1,%2,%3};"
        : "+f"(c[0]), "+f"(c[1]), "+f"(c[2]), "+f"(c[3])
        : "r"(a0), "r"(a1), "r"(a2), "r"(a3), "r"(b0), "r"(b1));
}

// ---------------- prep: fold wa into Wq/Wk -> effective [16,256] matrices ---
__global__ void prep_kernel(const float* __restrict__ Wq_u, const float* __restrict__ bq_u,
                            const float* __restrict__ Wk_u, const float* __restrict__ bk_u,
                            const float* __restrict__ Wq_i, const float* __restrict__ bq_i,
                            const float* __restrict__ Wk_i, const float* __restrict__ bk_i,
                            const float* __restrict__ wa_u, const float* __restrict__ wa_i) {
    int b = blockIdx.x;  // 0:Wq_u 1:Wk_u 2:Wq_i 3:Wk_i
    const float* W    = (b == 0) ? Wq_u : (b == 1) ? Wk_u : (b == 2) ? Wq_i : Wk_i;
    const float* bias = (b == 0) ? bq_u : (b == 1) ? bk_u : (b == 2) ? bq_i : bk_i;
    const float* wa   = (b < 2) ? wa_u : wa_i;
    float* A  = (b < 2) ? g_A_u : g_A_i;
    float* be = (b < 2) ? g_beff_u : g_beff_i;
    int rowoff = (b & 1) * 8;
    int k = threadIdx.x;
    __shared__ float was[64];
    if (k < 64) was[k] = wa[k];
    __syncthreads();
#pragma unroll
    for (int h = 0; h < 8; h++) {
        float s = 0.f;
        for (int d = 0; d < 64; d++) s += W[(h * 64 + d) * 256 + k] * was[d];
        A[(rowoff + h) * 256 + k] = s;
    }
    if (k < 8) {
        float s = 0.f;
        for (int d = 0; d < 64; d++) s += bias[k * 64 + d] * was[d];
        be[rowoff + k] = s;
    }
}

// ---------------- attn projections: aq/ak = x @ A^T + beff  (16 outs/node) --
__global__ void attnproj_kernel(const float* __restrict__ X, int isUser) {
    const float* A  = isUser ? g_A_u : g_A_i;
    const float* be = isUser ? g_beff_u : g_beff_i;
    float* outp     = isUser ? g_aqk_u : g_aqk_i;
    __shared__ float xs[256];
    int n = blockIdx.x;
    xs[threadIdx.x] = X[(size_t)n * 256 + threadIdx.x];
    __syncthreads();
    int w = threadIdx.x >> 5, l = threadIdx.x & 31;
#pragma unroll
    for (int r = 0; r < 2; r++) {
        int j = w + r * 8;
        float s = 0.f;
#pragma unroll
        for (int c = 0; c < 8; c++) {
            int k = l + 32 * c;
            s += xs[k] * A[j * 256 + k];
        }
#pragma unroll
        for (int off = 16; off; off >>= 1) s += __shfl_down_sync(0xffffffffu, s, off);
        if (l == 0) outp[n * 16 + j] = s + be[j];
    }
}

// ---------------- V GEMM via mma.sync tf32 ----------------------------------
// C[M,512] = X[M,256] @ W[512,256]^T + b.
// CTA tile 128(m) x 64(n), K staged 32 at a time, 8 warps in 4(m) x 2(n).
// Each warp: 32x32 via 2x4 m16n8k8 fragments.
__global__ void __launch_bounds__(256) gemm_mma_kernel(const float* __restrict__ X,
                                                       const float* __restrict__ W,
                                                       const float* __restrict__ bias,
                                                       int isUser, int M) {
    float* C = isUser ? g_v_u : g_v_i;
    __shared__ uint32_t As[128][36];
    __shared__ uint32_t Bs[64][36];
    __shared__ float s_bias[64];

    int tid = threadIdx.x, lane = tid & 31, warp = tid >> 5;
    int wm = (warp & 3) * 32;         // warp m offset in tile
    int wn = (warp >> 2) * 32;        // warp n offset in tile
    int n0 = blockIdx.x * 64;
    int m0 = blockIdx.y * 128;
    int lq = lane >> 2;               // 0..7
    int lr = lane & 3;                // 0..3

    if (tid < 64) s_bias[tid] = bias[n0 + tid];

    float acc[2][4][4];
#pragma unroll
    for (int mt = 0; mt < 2; mt++)
#pragma unroll
        for (int nt = 0; nt < 4; nt++)
#pragma unroll
            for (int i = 0; i < 4; i++) acc[mt][nt][i] = 0.f;

    for (int c = 0; c < 8; c++) {
        // stage A: 128 rows x 32 cols
        {
            int row = tid >> 1, seg = (tid & 1) * 16;
            int gr = m0 + row;
            if (gr >= M) gr = M - 1;
            const float* p = X + (size_t)gr * 256 + c * 32 + seg;
#pragma unroll
            for (int q = 0; q < 4; q++) {
                float4 v = *(const float4*)(p + q * 4);
                As[row][seg + q * 4 + 0] = to_tf32(v.x);
                As[row][seg + q * 4 + 1] = to_tf32(v.y);
                As[row][seg + q * 4 + 2] = to_tf32(v.z);
                As[row][seg + q * 4 + 3] = to_tf32(v.w);
            }
        }
        // stage B: 64 rows (n) x 32 cols (k)
        {
            int row = tid >> 2, seg = (tid & 3) * 8;
            const float* p = W + (size_t)(n0 + row) * 256 + c * 32 + seg;
#pragma unroll
            for (int q = 0; q < 2; q++) {
                float4 v = *(const float4*)(p + q * 4);
                Bs[row][seg + q * 4 + 0] = to_tf32(v.x);
                Bs[row][seg + q * 4 + 1] = to_tf32(v.y);
                Bs[row][seg + q * 4 + 2] = to_tf32(v.z);
                Bs[row][seg + q * 4 + 3] = to_tf32(v.w);
            }
        }
        __syncthreads();

#pragma unroll
        for (int kk = 0; kk < 4; kk++) {
            int k0 = kk * 8;
            uint32_t b[4][2];
#pragma unroll
            for (int nt = 0; nt < 4; nt++) {
                int n = wn + nt * 8 + lq;
                b[nt][0] = Bs[n][k0 + lr];
                b[nt][1] = Bs[n][k0 + lr + 4];
            }
#pragma unroll
            for (int mt = 0; mt < 2; mt++) {
                int r0 = wm + mt * 16 + lq;
                uint32_t a0 = As[r0][k0 + lr];
                uint32_t a1 = As[r0 + 8][k0 + lr];
                uint32_t a2 = As[r0][k0 + lr + 4];
                uint32_t a3 = As[r0 + 8][k0 + lr + 4];
#pragma unroll
                for (int nt = 0; nt < 4; nt++)
                    mma_tf32(acc[mt][nt], a0, a1, a2, a3, b[nt][0], b[nt][1]);
            }
        }
        __syncthreads();
    }

    // epilogue: c0,c1 -> (row, col), (row, col+1); c2,c3 -> row+8
#pragma unroll
    for (int mt = 0; mt < 2; mt++) {
        int row = m0 + wm + mt * 16 + lq;
#pragma unroll
        for (int nt = 0; nt < 4; nt++) {
            int cl = wn + nt * 8 + 2 * lr;    // col within 64-tile
            float bx = s_bias[cl], by = s_bias[cl + 1];
            if (row < M) {
                float2 o = make_float2(acc[mt][nt][0] + bx, acc[mt][nt][1] + by);
                *(float2*)(C + (size_t)row * 512 + n0 + cl) = o;
            }
            if (row + 8 < M) {
                float2 o = make_float2(acc[mt][nt][2] + bx, acc[mt][nt][3] + by);
                *(float2*)(C + (size_t)(row + 8) * 512 + n0 + cl) = o;
            }
        }
    }
}

// ---------------- edge phase ----------------
__global__ void score_kernel(const int* __restrict__ src, const int* __restrict__ dst,
                             int srcUser, int dstUser, int E) {
    int e = blockIdx.x * blockDim.x + threadIdx.x;
    if (e >= E) return;
    const float* aqk_s = srcUser ? g_aqk_u : g_aqk_i;
    const float* aqk_d = dstUser ? g_aqk_u : g_aqk_i;
    int s = src[e], d = dst[e];
    float4 ak0 = *(const float4*)(aqk_s + s * 16 + 8);
    float4 ak1 = *(const float4*)(aqk_s + s * 16 + 12);
    float4 aq0 = *(const float4*)(aqk_d + d * 16);
    float4 aq1 = *(const float4*)(aqk_d + d * 16 + 4);
    float sc[8];
    sc[0] = (ak0.x + aq0.x) * 0.125f; sc[1] = (ak0.y + aq0.y) * 0.125f;
    sc[2] = (ak0.z + aq0.z) * 0.125f; sc[3] = (ak0.w + aq0.w) * 0.125f;
    sc[4] = (ak1.x + aq1.x) * 0.125f; sc[5] = (ak1.y + aq1.y) * 0.125f;
    sc[6] = (ak1.z + aq1.z) * 0.125f; sc[7] = (ak1.w + aq1.w) * 0.125f;
    *(float4*)(g_edge + e * 8)     = make_float4(sc[0], sc[1], sc[2], sc[3]);
    *(float4*)(g_edge + e * 8 + 4) = make_float4(sc[4], sc[5], sc[6], sc[7]);
#pragma unroll
    for (int h = 0; h < 8; h++) atomicMax(&g_mkey[d * 8 + h], fkey(sc[h]));
    atomicAdd(&g_deg[d], 1.0f);
}

__global__ void exp_kernel(const int* __restrict__ dst, int E) {
    int e = blockIdx.x * blockDim.x + threadIdx.x;
    if (e >= E) return;
    int d = dst[e];
    float4 s0 = *(const float4*)(g_edge + e * 8);
    float4 s1 = *(const float4*)(g_edge + e * 8 + 4);
    float sc[8] = {s0.x, s0.y, s0.z, s0.w, s1.x, s1.y, s1.z, s1.w};
    float ex[8];
#pragma unroll
    for (int h = 0; h < 8; h++) {
        float m = keyf(g_mkey[d * 8 + h]);
        ex[h] = __expf(sc[h] - m);
        atomicAdd(&g_den[d * 8 + h], ex[h]);
    }
    *(float4*)(g_edge + e * 8)     = make_float4(ex[0], ex[1], ex[2], ex[3]);
    *(float4*)(g_edge + e * 8 + 4) = make_float4(ex[4], ex[5], ex[6], ex[7]);
}

__global__ void attn_kernel(const int* __restrict__ dst, int E) {
    int e = blockIdx.x * blockDim.x + threadIdx.x;
    if (e >= E) return;
    int d = dst[e];
    float id = 1.0f / fmaxf(g_deg[d], 1.0f);
    float4 e0 = *(const float4*)(g_edge + e * 8);
    float4 e1 = *(const float4*)(g_edge + e * 8 + 4);
    float ex[8] = {e0.x, e0.y, e0.z, e0.w, e1.x, e1.y, e1.z, e1.w};
    float a[8];
#pragma unroll
    for (int h = 0; h < 8; h++) a[h] = ex[h] / g_den[d * 8 + h] * id;
    *(float4*)(g_edge + e * 8)     = make_float4(a[0], a[1], a[2], a[3]);
    *(float4*)(g_edge + e * 8 + 4) = make_float4(a[4], a[5], a[6], a[7]);
}

// message scatter: one thread per (edge, float4-quad); contiguous 2KB per edge
__global__ void msg_kernel(const int* __restrict__ src, const int* __restrict__ dst,
                           int srcUser, float* __restrict__ outp, int E) {
    int idx = blockIdx.x * blockDim.x + threadIdx.x;
    if (idx >= E * 128) return;
    int e = idx >> 7, q = idx & 127;
    int h = q >> 4;
    const float* v = srcUser ? g_v_u : g_v_i;
    int s = src[e], d = dst[e];
    float a = g_edge[e * 8 + h];
    float4 vv = *(const float4*)(v + (size_t)s * 512 + q * 4);
    float x = vv.x * a, y = vv.y * a, z = vv.z * a, w = vv.w * a;
    float* p = outp + (size_t)d * 512 + q * 4;
    asm volatile("red.global.add.v4.f32 [%0], {%1,%2,%3,%4};"
                 :: "l"(p), "f"(x), "f"(y), "f"(z), "f"(w)
                 : "memory");
}

// ---------------- host ----------------
static void run_etype(const int* src, const int* dst, int srcUser, int dstUser,
                      float* outp, int Nd, int E,
                      void* p_mkey, void* p_den, void* p_deg) {
    cudaMemsetAsync(p_mkey, 0, (size_t)Nd * 8 * sizeof(unsigned));
    cudaMemsetAsync(p_den, 0, (size_t)Nd * 8 * sizeof(float));
    cudaMemsetAsync(p_deg, 0, (size_t)Nd * sizeof(float));
    int gb = (E + 255) / 256;
    score_kernel<<<gb, 256>>>(src, dst, srcUser, dstUser, E);
    exp_kernel<<<gb, 256>>>(dst, E);
    attn_kernel<<<gb, 256>>>(dst, E);
    msg_kernel<<<(E * 128 + 255) / 256, 256>>>(src, dst, srcUser, outp, E);
}

extern "C" void kernel_launch(void* const* d_in, const int* in_sizes, int n_in,
                              void* d_out, int out_size) {
    const float* x_u  = (const float*)d_in[0];
    const float* x_i  = (const float*)d_in[1];
    const float* Wq_u = (const float*)d_in[2];  const float* bq_u = (const float*)d_in[3];
    const float* Wk_u = (const float*)d_in[4];  const float* bk_u = (const float*)d_in[5];
    const float* Wv_u = (const float*)d_in[6];  const float* bv_u = (const float*)d_in[7];
    const float* Wq_i = (const float*)d_in[8];  const float* bq_i = (const float*)d_in[9];
    const float* Wk_i = (const float*)d_in[10]; const float* bk_i = (const float*)d_in[11];
    const float* Wv_i = (const float*)d_in[12]; const float* bv_i = (const float*)d_in[13];
    const float* wa_u = (const float*)d_in[14]; const float* wa_i = (const float*)d_in[15];
    const int* src_c  = (const int*)d_in[16];   const int* dst_c  = (const int*)d_in[17];
    const int* src_cb = (const int*)d_in[18];   const int* dst_cb = (const int*)d_in[19];
    const int* src_f  = (const int*)d_in[20];   const int* dst_f  = (const int*)d_in[21];

    int NU = in_sizes[0] / 256;
    int NI = in_sizes[1] / 256;
    int E  = in_sizes[16];

    float* out_user = (float*)d_out;
    float* out_item = out_user + (size_t)NU * 512;

    void *p_mkey, *p_den, *p_deg;
    cudaGetSymbolAddress(&p_mkey, g_mkey);
    cudaGetSymbolAddress(&p_den, g_den);
    cudaGetSymbolAddress(&p_deg, g_deg);

    cudaMemsetAsync(d_out, 0, (size_t)(NU + NI) * 512 * sizeof(float));

    prep_kernel<<<4, 256>>>(Wq_u, bq_u, Wk_u, bk_u, Wq_i, bq_i, Wk_i, bk_i, wa_u, wa_i);
    attnproj_kernel<<<NU, 256>>>(x_u, 1);
    attnproj_kernel<<<NI, 256>>>(x_i, 0);
    gemm_mma_kernel<<<dim3(8, (NU + 127) / 128), 256>>>(x_u, Wv_u, bv_u, 1, NU);
    gemm_mma_kernel<<<dim3(8, (NI + 127) / 128), 256>>>(x_i, Wv_i, bv_i, 0, NI);

    // ('user','clicks','item'): src=user, dst=item -> h_item
    run_etype(src_c, dst_c, 1, 0, out_item, NI, E, p_mkey, p_den, p_deg);
    // ('item','clicked_by','user'): src=item, dst=user -> h_user
    run_etype(src_cb, dst_cb, 0, 1, out_user, NU, E, p_mkey, p_den, p_deg);
    // ('user','follows','user') -> h_user (accumulates)
    run_etype(src_f, dst_f, 1, 1, out_user, NU, E, p_mkey, p_den, p_deg);
}